// round 2
// baseline (speedup 1.0000x reference)
#include <cuda_runtime.h>
#include <math.h>

// LSTM: B=256, T=512, D=256, H=1024, C=128
// Strategy: persistent kernel, 1 grid barrier per timestep.
// Per step: preact[256,4096] = [x_t | h] (K=1280) @ Wcat (1280x4096, columns
// interleaved n = j*4 + g so each CTA tile owns all 4 gates of its hidden units),
// then in-register gate math updates c/h. fp32 FFMA baseline.

#define BB   256
#define TT   512
#define DD   256
#define HH   1024
#define CCC  128
#define KTOT 1280
#define NTOT 4096
#define GRID 128
#define MB   64
#define NB   128
#define KB   32

__device__ float    g_Wcat[KTOT * NTOT];   // 21 MB
__device__ float    g_bcat[NTOT];
__device__ float    g_h[BB * HH];
__device__ float    g_c[BB * HH];
__device__ unsigned g_bar;

// ---------------------------------------------------------------------------
// Init: zero state, reset barrier, repack weights/biases into interleaved Wcat.
// Column n = j*4 + g  (g: 0=g(tanh) 1=i 2=f 3=o). Rows 0..255 = Wx, 256.. = Wh.
// ---------------------------------------------------------------------------
__global__ void lstm_init_kernel(
    const float* __restrict__ Wgx, const float* __restrict__ Wgh,
    const float* __restrict__ Wix, const float* __restrict__ Wih,
    const float* __restrict__ Wfx, const float* __restrict__ Wfh,
    const float* __restrict__ Wox, const float* __restrict__ Woh,
    const float* __restrict__ bg,  const float* __restrict__ bi,
    const float* __restrict__ bf,  const float* __restrict__ bo)
{
    const long total = (long)KTOT * NTOT;
    for (long idx = (long)blockIdx.x * blockDim.x + threadIdx.x; idx < total;
         idx += (long)gridDim.x * blockDim.x) {
        int k = (int)(idx / NTOT);
        int n = (int)(idx % NTOT);
        int j = n >> 2;
        int g = n & 3;
        if (k < DD) {
            const float* src = (g == 0) ? Wgx : (g == 1) ? Wix : (g == 2) ? Wfx : Wox;
            g_Wcat[idx] = src[(size_t)k * HH + j];
        } else {
            const float* src = (g == 0) ? Wgh : (g == 1) ? Wih : (g == 2) ? Wfh : Woh;
            g_Wcat[idx] = src[(size_t)(k - DD) * HH + j];
        }
        if (idx < (long)BB * HH) { g_h[idx] = 0.0f; g_c[idx] = 0.0f; }
        if (idx < NTOT) {
            const float* bsrc = (g == 0) ? bg : (g == 1) ? bi : (g == 2) ? bf : bo;
            g_bcat[idx] = bsrc[j];
        }
        if (idx == 0) g_bar = 0u;
    }
}

// ---------------------------------------------------------------------------
// Grid barrier: CG-style release-arrive / acquire-spin. 128 CTAs, single wave.
// ---------------------------------------------------------------------------
__device__ __forceinline__ void grid_sync(unsigned target)
{
    __syncthreads();
    if (threadIdx.x == 0) {
        asm volatile("red.release.gpu.global.add.u32 [%0], %1;"
                     :: "l"(&g_bar), "r"(1u) : "memory");
        unsigned v;
        do {
            asm volatile("ld.acquire.gpu.global.u32 %0, [%1];"
                         : "=r"(v) : "l"(&g_bar) : "memory");
        } while (v < target);
    }
    __syncthreads();
}

__device__ __forceinline__ float sigmoidf_(float x)
{
    return 1.0f / (1.0f + expf(-x));
}

// ---------------------------------------------------------------------------
// Persistent LSTM kernel. Grid = 128 CTAs x 256 threads.
// CTA tile: MB=64 batch rows x NB=128 interleaved columns (= 32 hidden units x 4 gates).
// Thread (tx=tid&15, ty=tid>>4): 4 rows x 8 cols -> owns 2 hidden units x 4 rows.
// ---------------------------------------------------------------------------
__global__ void __launch_bounds__(256, 1) lstm_persistent_kernel(
    const float* __restrict__ x,
    const float* __restrict__ Wph,
    const float* __restrict__ bp,
    float* __restrict__ out)
{
    __shared__ float As[MB][KB + 4];   // [64][36] — pad keeps float4 STS 16B-aligned
    __shared__ float Bs[KB][NB];       // [32][128]

    const int tid = threadIdx.x;
    const int tx  = tid & 15;
    const int ty  = tid >> 4;
    const int ty4 = ty * 4;
    const int bm  = blockIdx.x >> 5;   // 0..3   (M tiles)
    const int bn  = blockIdx.x & 31;   // 0..31  (N tiles)
    const int m0  = bm * MB;
    const int n0  = bn * NB;
    const int j0  = n0 >> 2;           // hidden-unit base for this tile

    // bias for this thread's 8 columns (constant across t)
    float bias[8];
#pragma unroll
    for (int i = 0; i < 8; i++) bias[i] = g_bcat[n0 + tx * 8 + i];

    for (int t = 0; t < TT; t++) {
        float acc[4][8];
#pragma unroll
        for (int r = 0; r < 4; r++)
#pragma unroll
            for (int i = 0; i < 8; i++) acc[r][i] = 0.0f;

        for (int kc = 0; kc < KTOT / KB; kc++) {
            const int k0 = kc * KB;

            // ---- load A tile (64 x 32): rows = batch, k<256 from x_t, else from h
#pragma unroll
            for (int i = 0; i < 2; i++) {
                int e4 = tid * 2 + i;            // 0..511
                int m  = e4 >> 3;                // 0..63
                int k4 = (e4 & 7) * 4;           // 0..28
                int kg = k0 + k4;
                float4 v;
                if (kg < DD) {
                    v = *(const float4*)(x + ((size_t)(m0 + m) * TT + t) * DD + kg);
                } else {
                    v = *(const float4*)(g_h + (size_t)(m0 + m) * HH + (kg - DD));
                }
                *(float4*)&As[m][k4] = v;
            }
            // ---- load B tile (32 x 128) from Wcat
#pragma unroll
            for (int i = 0; i < 4; i++) {
                int e4 = tid + i * 256;          // 0..1023
                int kk = e4 >> 5;                // 0..31
                int nn = (e4 & 31) * 4;          // 0..124
                *(float4*)&Bs[kk][nn] =
                    *(const float4*)(g_Wcat + (size_t)(k0 + kk) * NTOT + n0 + nn);
            }
            __syncthreads();

            // ---- FFMA micro-kernel
#pragma unroll 4
            for (int kk = 0; kk < KB; kk++) {
                float a0 = As[ty4 + 0][kk];
                float a1 = As[ty4 + 1][kk];
                float a2 = As[ty4 + 2][kk];
                float a3 = As[ty4 + 3][kk];
                float4 q0 = *(const float4*)&Bs[kk][tx * 8];
                float4 q1 = *(const float4*)&Bs[kk][tx * 8 + 4];
                float bv[8] = {q0.x, q0.y, q0.z, q0.w, q1.x, q1.y, q1.z, q1.w};
#pragma unroll
                for (int i = 0; i < 8; i++) {
                    acc[0][i] += a0 * bv[i];
                    acc[1][i] += a1 * bv[i];
                    acc[2][i] += a2 * bv[i];
                    acc[3][i] += a3 * bv[i];
                }
            }
            __syncthreads();
        }

        // ---- gate math + state update (all in-register; this thread owns its cells)
#pragma unroll
        for (int r = 0; r < 4; r++) {
            const int m = m0 + ty4 + r;
#pragma unroll
            for (int jj = 0; jj < 2; jj++) {
                const int j = j0 + tx * 2 + jj;
                float pg = acc[r][jj * 4 + 0] + bias[jj * 4 + 0];
                float pi = acc[r][jj * 4 + 1] + bias[jj * 4 + 1];
                float pf = acc[r][jj * 4 + 2] + bias[jj * 4 + 2];
                float po = acc[r][jj * 4 + 3] + bias[jj * 4 + 3];
                float gt = tanhf(pg);
                float it = sigmoidf_(pi);
                float ft = sigmoidf_(pf);
                float ot = sigmoidf_(po);
                size_t idx = (size_t)m * HH + j;
                float cn = gt * it + g_c[idx] * ft;
                float hn = tanhf(cn) * ot;
                g_c[idx] = cn;
                g_h[idx] = hn;
            }
        }

        grid_sync((unsigned)(t + 1) * GRID);
    }

    // ---- final projection: out[b][cc] = h[b] . Wph[:,cc] + bp[cc]
    // exactly 128*256 = 32768 threads = 256x128 outputs
    const int gidx = blockIdx.x * blockDim.x + tid;
    const int b  = gidx >> 7;
    const int cc = gidx & 127;
    const float* hrow = g_h + (size_t)b * HH;
    float s = 0.0f;
#pragma unroll 8
    for (int k = 0; k < HH; k++) s += hrow[k] * Wph[(size_t)k * CCC + cc];
    out[gidx] = s + bp[cc];
}

// ---------------------------------------------------------------------------
extern "C" void kernel_launch(void* const* d_in, const int* in_sizes, int n_in,
                              void* d_out, int out_size)
{
    (void)in_sizes; (void)n_in; (void)out_size;
    const float* x   = (const float*)d_in[0];
    const float* Wgx = (const float*)d_in[1];
    const float* Wgh = (const float*)d_in[2];
    const float* bg  = (const float*)d_in[3];
    const float* Wix = (const float*)d_in[4];
    const float* Wih = (const float*)d_in[5];
    const float* bi  = (const float*)d_in[6];
    const float* Wfx = (const float*)d_in[7];
    const float* Wfh = (const float*)d_in[8];
    const float* bf  = (const float*)d_in[9];
    const float* Wox = (const float*)d_in[10];
    const float* Woh = (const float*)d_in[11];
    const float* bo  = (const float*)d_in[12];
    const float* Wph = (const float*)d_in[13];
    const float* bp  = (const float*)d_in[14];

    lstm_init_kernel<<<1024, 256>>>(Wgx, Wgh, Wix, Wih, Wfx, Wfh, Wox, Woh,
                                    bg, bi, bf, bo);
    lstm_persistent_kernel<<<GRID, 256>>>(x, Wph, bp, (float*)d_out);
}

// round 5
// speedup vs baseline: 3.9479x; 3.9479x over previous
#include <cuda_runtime.h>
#include <cuda_bf16.h>
#include <math.h>
#include <stdint.h>

// LSTM B=256,T=512,D=256,H=1024,C=128.
// Persistent kernel on mma.sync bf16 (bf16x3 split => ~fp32 accuracy), fp32 accum.
// 128 CTAs = 2 Mtiles(128) x 64 Ntiles(64); grid barrier per timestep.
// h double-buffered across steps to kill the write-while-read race.

#define BB   256
#define TT   512
#define DD   256
#define HH   1024
#define CCC  128
#define KTOT 1280
#define NTOT 4096
#define GRID 128
#define NTH  256
#define KBLK 64
#define NKB  (KTOT / KBLK)   // 20

// dynamic smem: two stages of {A_hi 16K, A_lo 16K, W_hi 8K, W_lo 8K}
#define STG_STRIDE 49152
#define OFF_A_HI   0
#define OFF_A_LO   16384
#define OFF_W_HI   32768
#define OFF_W_LO   40960
#define SMEM_TOTAL (2 * STG_STRIDE)

#define SW(o) ((o) ^ (((o) >> 3) & 0x70))

// ---------------- device globals ----------------
__device__ __nv_bfloat16 g_Whi[(size_t)NTOT * KTOT];
__device__ __nv_bfloat16 g_Wlo[(size_t)NTOT * KTOT];
__device__ float         g_bcat[NTOT];
__device__ __nv_bfloat16 g_xhi[(size_t)TT * BB * DD];
__device__ __nv_bfloat16 g_xlo[(size_t)TT * BB * DD];
__device__ __nv_bfloat16 g_hhi[2][BB * HH];   // double-buffered across steps
__device__ __nv_bfloat16 g_hlo[2][BB * HH];
__device__ float         g_hf[BB * HH];
__device__ unsigned      g_bar;

// ---------------- PTX helpers ----------------
__device__ __forceinline__ uint32_t smem_to_u32(const void* p) {
    uint32_t a;
    asm("{ .reg .u64 t; cvta.to.shared.u64 t, %1; cvt.u32.u64 %0, t; }" : "=r"(a) : "l"(p));
    return a;
}

#define CP16(dst, src) \
    asm volatile("cp.async.cg.shared.global [%0], [%1], 16;" :: "r"(dst), "l"(src) : "memory")
#define CP_COMMIT() asm volatile("cp.async.commit_group;" ::: "memory")
#define CP_WAIT0()  asm volatile("cp.async.wait_group 0;" ::: "memory")
#define CP_WAIT1()  asm volatile("cp.async.wait_group 1;" ::: "memory")

#define LDSM_X4(r0, r1, r2, r3, addr) \
    asm volatile("ldmatrix.sync.aligned.m8n8.x4.shared.b16 {%0,%1,%2,%3}, [%4];" \
                 : "=r"(r0), "=r"(r1), "=r"(r2), "=r"(r3) : "r"(addr))

#define MMA_BF16(c, a, b) \
    asm volatile("mma.sync.aligned.m16n8k16.row.col.f32.bf16.bf16.f32 " \
                 "{%0,%1,%2,%3},{%4,%5,%6,%7},{%8,%9},{%0,%1,%2,%3};" \
                 : "+f"((c)[0]), "+f"((c)[1]), "+f"((c)[2]), "+f"((c)[3]) \
                 : "r"((a)[0]), "r"((a)[1]), "r"((a)[2]), "r"((a)[3]), \
                   "r"((b)[0]), "r"((b)[1]))

// ---------------- column interleave mapping ----------------
// Within each 32-col warp tile: col(u,g) = 16*(u>>2) + 8*(g>>1) + 2*(u&3) + (g&1)
// => u = ((o>>4)<<2) + ((o>>1)&3),  g = ((o>>3)&1)*2 + (o&1)
// Global: n = w32*32 + o,  hidden j = w32*8 + u.

// ---------------- init kernels ----------------
__global__ void pack_w_kernel(
    const float* __restrict__ Wgx, const float* __restrict__ Wgh,
    const float* __restrict__ Wix, const float* __restrict__ Wih,
    const float* __restrict__ Wfx, const float* __restrict__ Wfh,
    const float* __restrict__ Wox, const float* __restrict__ Woh,
    const float* __restrict__ bg,  const float* __restrict__ bi,
    const float* __restrict__ bf,  const float* __restrict__ bo)
{
    const long total = (long)NTOT * KTOT;
    for (long idx = (long)blockIdx.x * blockDim.x + threadIdx.x; idx < total;
         idx += (long)gridDim.x * blockDim.x) {
        int n = (int)(idx / KTOT);
        int k = (int)(idx % KTOT);
        int o = n & 31;
        int w32 = n >> 5;
        int u = ((o >> 4) << 2) + ((o >> 1) & 3);
        int g = ((o >> 3) & 1) * 2 + (o & 1);
        int j = w32 * 8 + u;
        float w;
        if (k < DD) {
            const float* src = (g == 0) ? Wgx : (g == 1) ? Wix : (g == 2) ? Wfx : Wox;
            w = src[(size_t)k * HH + j];
        } else {
            const float* src = (g == 0) ? Wgh : (g == 1) ? Wih : (g == 2) ? Wfh : Woh;
            w = src[(size_t)(k - DD) * HH + j];
        }
        __nv_bfloat16 hi = __float2bfloat16(w);
        g_Whi[idx] = hi;
        g_Wlo[idx] = __float2bfloat16(w - __bfloat162float(hi));

        // bias: re-derive (j,g) from idx itself treated as the column index n
        if (idx < NTOT) {
            int nb  = (int)idx;
            int ob  = nb & 31;
            int wb  = nb >> 5;
            int ub  = ((ob >> 4) << 2) + ((ob >> 1) & 3);
            int gb  = ((ob >> 3) & 1) * 2 + (ob & 1);
            int jb  = wb * 8 + ub;
            const float* bsrc = (gb == 0) ? bg : (gb == 1) ? bi : (gb == 2) ? bf : bo;
            g_bcat[nb] = bsrc[jb];
        }
        if (idx < (long)BB * HH) {
            g_hhi[0][idx] = __float2bfloat16(0.0f);
            g_hlo[0][idx] = __float2bfloat16(0.0f);
            g_hhi[1][idx] = __float2bfloat16(0.0f);
            g_hlo[1][idx] = __float2bfloat16(0.0f);
        }
        if (idx == 0) g_bar = 0u;
    }
}

__global__ void pack_x_kernel(const float* __restrict__ x)
{
    const long total = (long)TT * BB * DD;
    for (long idx = (long)blockIdx.x * blockDim.x + threadIdx.x; idx < total;
         idx += (long)gridDim.x * blockDim.x) {
        int t = (int)(idx / (BB * DD));
        int r = (int)(idx % (BB * DD));
        int b = r / DD;
        int d = r % DD;
        float v = x[((size_t)b * TT + t) * DD + d];
        __nv_bfloat16 hi = __float2bfloat16(v);
        g_xhi[idx] = hi;
        g_xlo[idx] = __float2bfloat16(v - __bfloat162float(hi));
    }
}

// ---------------- grid barrier ----------------
__device__ __forceinline__ void grid_sync(unsigned target)
{
    __syncthreads();
    if (threadIdx.x == 0) {
        asm volatile("red.release.gpu.global.add.u32 [%0], %1;" :: "l"(&g_bar), "r"(1u) : "memory");
        unsigned v;
        do {
            asm volatile("ld.acquire.gpu.global.u32 %0, [%1];" : "=r"(v) : "l"(&g_bar) : "memory");
        } while (v < target);
    }
    __syncthreads();
}

__device__ __forceinline__ float sigf(float x) { return 1.0f / (1.0f + __expf(-x)); }
__device__ __forceinline__ float tanhfast(float x) { return 2.0f * sigf(2.0f * x) - 1.0f; }

// ---------------- staging: gmem -> smem via cp.async ----------------
__device__ __forceinline__ void stage_load(uint32_t sb, int t, int m0, int n0,
                                           int k0, int tid,
                                           const __nv_bfloat16* __restrict__ hhi,
                                           const __nv_bfloat16* __restrict__ hlo)
{
#pragma unroll
    for (int i = 0; i < 4; i++) {
        int idx = tid + i * NTH;       // 0..1023
        int row = idx >> 3;            // 0..127
        int q   = idx & 7;
        const __nv_bfloat16 *ph, *pl;
        if (k0 < DD) {
            size_t o = ((size_t)t * BB + (m0 + row)) * DD + k0 + q * 8;
            ph = g_xhi + o; pl = g_xlo + o;
        } else {
            size_t o = (size_t)(m0 + row) * HH + (k0 - DD) + q * 8;
            ph = hhi + o; pl = hlo + o;
        }
        uint32_t d = SW(row * 128 + q * 16);
        CP16(sb + OFF_A_HI + d, ph);
        CP16(sb + OFF_A_LO + d, pl);
    }
#pragma unroll
    for (int i = 0; i < 2; i++) {
        int idx = tid + i * NTH;       // 0..511
        int row = idx >> 3;            // 0..63
        int q   = idx & 7;
        size_t o = (size_t)(n0 + row) * KTOT + k0 + q * 8;
        uint32_t d = SW(row * 128 + q * 16);
        CP16(sb + OFF_W_HI + d, g_Whi + o);
        CP16(sb + OFF_W_LO + d, g_Wlo + o);
    }
}

// ---------------- per-stage compute: 64-K slab, 3 split terms ----------------
__device__ __forceinline__ void compute_stage(uint32_t sb, int lane, int m0w, int n0w,
                                              float acc[2][4][4])
{
    const int rowA = m0w + (lane & 15);
    const int colA = (lane >> 4) * 16;
    const int rowB = n0w + (lane & 15);
    const int colB = (lane >> 4) * 16;

#pragma unroll
    for (int k16 = 0; k16 < 4; k16++) {
        uint32_t ahi[2][4], alo[2][4];
#pragma unroll
        for (int mf = 0; mf < 2; mf++) {
            int off = (rowA + mf * 16) * 128 + colA + k16 * 32;
            LDSM_X4(ahi[mf][0], ahi[mf][1], ahi[mf][2], ahi[mf][3], sb + OFF_A_HI + SW(off));
            LDSM_X4(alo[mf][0], alo[mf][1], alo[mf][2], alo[mf][3], sb + OFF_A_LO + SW(off));
        }
        // W is [n][k] k-contiguous: NON-trans ldmatrix over n-rows yields the
        // exact mma.sync B fragment (lane -> W[n=lane/4][k=2*(lane%4)+{0,1}]).
        uint32_t whi[4][2], wlo[4][2];
#pragma unroll
        for (int nn = 0; nn < 2; nn++) {
            int off = (rowB + nn * 16) * 128 + colB + k16 * 32;
            uint32_t r0, r1, r2, r3;
            LDSM_X4(r0, r1, r2, r3, sb + OFF_W_HI + SW(off));
            whi[nn * 2 + 0][0] = r0; whi[nn * 2 + 0][1] = r2;
            whi[nn * 2 + 1][0] = r1; whi[nn * 2 + 1][1] = r3;
            LDSM_X4(r0, r1, r2, r3, sb + OFF_W_LO + SW(off));
            wlo[nn * 2 + 0][0] = r0; wlo[nn * 2 + 0][1] = r2;
            wlo[nn * 2 + 1][0] = r1; wlo[nn * 2 + 1][1] = r3;
        }
#pragma unroll
        for (int mf = 0; mf < 2; mf++)
#pragma unroll
            for (int nf = 0; nf < 4; nf++) {
                MMA_BF16(acc[mf][nf], ahi[mf], whi[nf]);
                MMA_BF16(acc[mf][nf], ahi[mf], wlo[nf]);
                MMA_BF16(acc[mf][nf], alo[mf], whi[nf]);
            }
    }
}

// ---------------- persistent LSTM kernel ----------------
__global__ void __launch_bounds__(NTH, 1) lstm_mma_kernel(
    const float* __restrict__ Wph, const float* __restrict__ bp, float* __restrict__ out)
{
    extern __shared__ char smem[];
    const uint32_t sbase = smem_to_u32(smem);
    const int tid  = threadIdx.x;
    const int wid  = tid >> 5;
    const int lane = tid & 31;
    const int m0w  = (wid >> 1) * 32;
    const int n0w  = (wid & 1) * 32;
    const int mt   = blockIdx.x >> 6;     // 0..1
    const int nt   = blockIdx.x & 63;     // 0..63
    const int m0   = mt * 128;
    const int n0   = nt * 64;
    const int j0   = nt * 16 + (n0w >> 2);
    const int gid  = lane >> 2;           // group id 0..7
    const int tid4 = lane & 3;

    // per-thread bias for owned (u2, gate) cells
    float biasr[2][4];
#pragma unroll
    for (int u2 = 0; u2 < 2; u2++)
#pragma unroll
        for (int g = 0; g < 4; g++) {
            int o = (u2 * 2 + (g >> 1)) * 8 + tid4 * 2 + (g & 1);
            biasr[u2][g] = g_bcat[n0 + n0w + o];
        }

    // c-state in registers: [mf][hr][u2]
    float cst[2][2][2];
#pragma unroll
    for (int a = 0; a < 2; a++)
#pragma unroll
        for (int b = 0; b < 2; b++)
#pragma unroll
            for (int cdx = 0; cdx < 2; cdx++) cst[a][b][cdx] = 0.0f;

    for (int t = 0; t < TT; t++) {
        const int rb = t & 1;           // read h buffer
        const int wb = rb ^ 1;          // write h buffer
        const __nv_bfloat16* hrd_hi = g_hhi[rb];
        const __nv_bfloat16* hrd_lo = g_hlo[rb];

        float acc[2][4][4];
#pragma unroll
        for (int mf = 0; mf < 2; mf++)
#pragma unroll
            for (int nf = 0; nf < 4; nf++)
#pragma unroll
                for (int e = 0; e < 4; e++) acc[mf][nf][e] = 0.0f;

        stage_load(sbase,              t, m0, n0, 0 * KBLK, tid, hrd_hi, hrd_lo); CP_COMMIT();
        stage_load(sbase + STG_STRIDE, t, m0, n0, 1 * KBLK, tid, hrd_hi, hrd_lo); CP_COMMIT();

        for (int kc = 0; kc < NKB; kc++) {
            if (kc < NKB - 1) CP_WAIT1(); else CP_WAIT0();
            __syncthreads();
            const uint32_t sb = sbase + (kc & 1) * STG_STRIDE;
            compute_stage(sb, lane, m0w, n0w, acc);
            __syncthreads();
            if (kc + 2 < NKB) {
                stage_load(sb, t, m0, n0, (kc + 2) * KBLK, tid, hrd_hi, hrd_lo);
                CP_COMMIT();
            }
        }

        // gate math + state update, all in-register
#pragma unroll
        for (int mf = 0; mf < 2; mf++)
#pragma unroll
            for (int hr = 0; hr < 2; hr++) {
                const int m = m0 + m0w + mf * 16 + gid + hr * 8;
#pragma unroll
                for (int u2 = 0; u2 < 2; u2++) {
                    float pg = acc[mf][u2 * 2 + 0][hr * 2 + 0] + biasr[u2][0];
                    float pi = acc[mf][u2 * 2 + 0][hr * 2 + 1] + biasr[u2][1];
                    float pf = acc[mf][u2 * 2 + 1][hr * 2 + 0] + biasr[u2][2];
                    float po = acc[mf][u2 * 2 + 1][hr * 2 + 1] + biasr[u2][3];
                    float gt = tanhfast(pg);
                    float it = sigf(pi);
                    float ft = sigf(pf);
                    float ot = sigf(po);
                    float cn = gt * it + cst[mf][hr][u2] * ft;
                    cst[mf][hr][u2] = cn;
                    float hv = tanhfast(cn) * ot;
                    const int j = j0 + u2 * 4 + tid4;
                    size_t o = (size_t)m * HH + j;
                    __nv_bfloat16 hh = __float2bfloat16(hv);
                    g_hhi[wb][o] = hh;
                    g_hlo[wb][o] = __float2bfloat16(hv - __bfloat162float(hh));
                    if (t == TT - 1) g_hf[o] = hv;
                }
            }

        grid_sync((unsigned)(t + 1) * GRID);
    }

    // final projection: out[b][cc] = g_hf[b] . Wph[:,cc] + bp[cc]
    {
        const int gidx = blockIdx.x * NTH + tid;   // 0..32767 = 256 x 128
        const int b  = gidx >> 7;
        const int cc = gidx & 127;
        const float* hrow = g_hf + (size_t)b * HH;
        float s = 0.0f;
#pragma unroll 8
        for (int k = 0; k < HH; k++) s += hrow[k] * Wph[(size_t)k * CCC + cc];
        out[gidx] = s + bp[cc];
    }
}

// ---------------- launch ----------------
extern "C" void kernel_launch(void* const* d_in, const int* in_sizes, int n_in,
                              void* d_out, int out_size)
{
    (void)in_sizes; (void)n_in; (void)out_size;
    const float* x   = (const float*)d_in[0];
    const float* Wgx = (const float*)d_in[1];
    const float* Wgh = (const float*)d_in[2];
    const float* bg  = (const float*)d_in[3];
    const float* Wix = (const float*)d_in[4];
    const float* Wih = (const float*)d_in[5];
    const float* bi  = (const float*)d_in[6];
    const float* Wfx = (const float*)d_in[7];
    const float* Wfh = (const float*)d_in[8];
    const float* bf  = (const float*)d_in[9];
    const float* Wox = (const float*)d_in[10];
    const float* Woh = (const float*)d_in[11];
    const float* bo  = (const float*)d_in[12];
    const float* Wph = (const float*)d_in[13];
    const float* bp  = (const float*)d_in[14];

    cudaFuncSetAttribute(lstm_mma_kernel, cudaFuncAttributeMaxDynamicSharedMemorySize, SMEM_TOTAL);

    pack_w_kernel<<<512, 256>>>(Wgx, Wgh, Wix, Wih, Wfx, Wfh, Wox, Woh, bg, bi, bf, bo);
    pack_x_kernel<<<2048, 256>>>(x);
    lstm_mma_kernel<<<GRID, NTH, SMEM_TOTAL>>>(Wph, bp, (float*)d_out);
}